// round 11
// baseline (speedup 1.0000x reference)
#include <cuda_runtime.h>
#include <cuda_fp16.h>
#include <math.h>
#include <stdint.h>

#define BATCH 8
#define TLEN  2048
#define DDIM  512
#define BLK   128
#define BLKK  64
#define NTILE (TLEN / BLK)                  // 16
#define NPAIRS (NTILE * (NTILE + 1) / 2)    // 136
#define NITER (DDIM / BLKK)                 // 8
#define TB    16384                         // operand tile: 128 rows x 128B
#define STAGE_BYTES (2 * TB)                // A, B = 32KB
#define NSTAGE 3
#define CPAD 129
#define SMEM_DYN (NSTAGE * STAGE_BYTES)     // 96KB

__device__ __align__(256) __half g_F[(size_t)BATCH * TLEN * DDIM];

static __device__ __forceinline__ uint32_t smem_u32(const void* p) {
    uint32_t a;
    asm("{ .reg .u64 t; cvta.to.shared.u64 t, %1; cvt.u32.u64 %0, t; }" : "=r"(a) : "l"(p));
    return a;
}

#define CP_ASYNC16(saddr, gptr) \
    asm volatile("cp.async.cg.shared.global [%0], [%1], 16;" :: "r"(saddr), "l"(gptr))
#define CP_COMMIT() asm volatile("cp.async.commit_group;" ::: "memory")
#define CP_WAIT(n)  asm volatile("cp.async.wait_group %0;" :: "n"(n) : "memory")

#define LDSM4(R, addr) \
    asm volatile("ldmatrix.sync.aligned.m8n8.x4.shared.b16 {%0,%1,%2,%3}, [%4];" \
        : "=r"((R)[0]), "=r"((R)[1]), "=r"((R)[2]), "=r"((R)[3]) : "r"(addr))

#define MMA16816(d, a, b0, b1) \
    asm volatile("mma.sync.aligned.m16n8k16.row.col.f32.f16.f16.f32 " \
        "{%0,%1,%2,%3},{%4,%5,%6,%7},{%8,%9},{%0,%1,%2,%3};" \
        : "+f"((d)[0]), "+f"((d)[1]), "+f"((d)[2]), "+f"((d)[3]) \
        : "r"((a)[0]), "r"((a)[1]), "r"((a)[2]), "r"((a)[3]), "r"(b0), "r"(b1))

// ---------------------------------------------------------------------------
// Kernel 1: per-row normalize -> fp16
// ---------------------------------------------------------------------------
__global__ void split_kernel(const float* __restrict__ X) {
    int row = blockIdx.x;
    const float4* xr = (const float4*)(X + (size_t)row * DDIM);
    float4 v = xr[threadIdx.x];  // 128 threads x 4 = 512
    float s = v.x * v.x + v.y * v.y + v.z * v.z + v.w * v.w;
#pragma unroll
    for (int o = 16; o; o >>= 1) s += __shfl_xor_sync(0xffffffffu, s, o);
    __shared__ float ws[4];
    if ((threadIdx.x & 31) == 0) ws[threadIdx.x >> 5] = s;
    __syncthreads();
    float tot = ws[0] + ws[1] + ws[2] + ws[3];
    float rn = 1.0f / fmaxf(sqrtf(tot), 1e-12f);

    __half2* Fp = (__half2*)(g_F + (size_t)row * DDIM + threadIdx.x * 4);
    Fp[0] = __floats2half2_rn(v.x * rn, v.y * rn);
    Fp[1] = __floats2half2_rn(v.z * rn, v.w * rn);
}

// ---------------------------------------------------------------------------
// Kernel 2: C = F F^T, fp16 HMMA
// 4 warps of 64x64; BLKK=64; 3-stage cp.async; fragment double-buffering
// ---------------------------------------------------------------------------
__global__ void __launch_bounds__(128, 2) gemm_kernel(float* __restrict__ out) {
    extern __shared__ __align__(1024) char smem[];
    const uint32_t sbase = smem_u32(smem);

    const int tid  = threadIdx.x;
    const int wid  = tid >> 5;
    const int lane = tid & 31;
    const int b    = blockIdx.y;
    const int lin  = blockIdx.x;

    int j = (int)((sqrtf(8.0f * (float)lin + 1.0f) - 1.0f) * 0.5f);
    while ((j + 1) * (j + 2) / 2 <= lin) j++;
    while (j * (j + 1) / 2 > lin) j--;
    const int i = lin - j * (j + 1) / 2;
    const int row0 = i * BLK;
    const int col0 = j * BLK;

    const __half* Fb = g_F + (size_t)b * TLEN * DDIM;

    const int c  = tid & 7;   // 16B chunk within 128B row
    const int r0 = tid >> 3;  // 0..15

#define ISSUE(itr) do {                                                        \
        const int kk_ = (itr) * BLKK;                                          \
        const uint32_t st_ = sbase + ((itr) % NSTAGE) * STAGE_BYTES;           \
        _Pragma("unroll")                                                      \
        for (int q = 0; q < 8; q++) {                                          \
            const int r = r0 + q * 16;                                         \
            const uint32_t so = (uint32_t)(r * 128 + ((c ^ (r & 7)) << 4));    \
            CP_ASYNC16(st_ + so,      Fb + (size_t)(row0 + r) * DDIM + kk_ + c * 8); \
            CP_ASYNC16(st_ + TB + so, Fb + (size_t)(col0 + r) * DDIM + kk_ + c * 8); \
        }                                                                      \
        CP_COMMIT();                                                           \
    } while (0)

    ISSUE(0); ISSUE(1); ISSUE(2);

    // warp grid: 2(m) x 2(n); warp tile 64(m) x 64(n)
    const int wm = (wid >> 1) * 64;
    const int wn = (wid & 1) * 64;
    const int lrow  = lane & 15;
    const int khalf = lane >> 4;

    // precomputed per-lane smem row offsets (swizzle depends on row only)
    uint32_t aoff[4], boff[4];
#pragma unroll
    for (int f = 0; f < 4; f++) {
        const int ra = wm + f * 16 + lrow;
        const int rb = wn + f * 16 + lrow;
        aoff[f] = ra * 128 + (((ra & 7)) << 4);       // xor with chunk applied later
        boff[f] = rb * 128 + (((rb & 7)) << 4);
    }
    // note: chunk xor: ((chunk0 ^ (row&7)) << 4) = (row&7)<<4 XOR chunk0<<4
    // since chunk0 in [0,7], xor in the shifted domain is exact.

#define LOAD_FRAGS(buf, st_, kk2) do {                                         \
        const uint32_t cx = (uint32_t)((kk2) * 2 + khalf) << 4;                \
        _Pragma("unroll")                                                      \
        for (int f = 0; f < 4; f++) {                                          \
            LDSM4(ah[buf][f], (st_) + (aoff[f] ^ cx));                         \
            LDSM4(bx[buf][f], (st_) + TB + (boff[f] ^ cx));                    \
        }                                                                      \
    } while (0)

#define MMA_BLOCK(buf) do {                                                    \
        _Pragma("unroll")                                                      \
        for (int mf = 0; mf < 4; mf++)                                         \
            _Pragma("unroll")                                                  \
            for (int nf = 0; nf < 8; nf++) {                                   \
                const int g = nf >> 1, o = nf & 1;                             \
                MMA16816(acc[mf][nf], ah[buf][mf], bx[buf][g][o], bx[buf][g][o + 2]); \
            }                                                                  \
    } while (0)

    float acc[4][8][4];
#pragma unroll
    for (int mf = 0; mf < 4; mf++)
#pragma unroll
        for (int nf = 0; nf < 8; nf++)
#pragma unroll
            for (int u = 0; u < 4; u++) acc[mf][nf][u] = 0.f;

    uint32_t ah[2][4][4], bx[2][4][4];

    for (int it = 0; it < NITER; it++) {
        CP_WAIT(1);
        __syncthreads();
        if (it + 2 < NITER) ISSUE(it + 2);

        const uint32_t st = sbase + (it % NSTAGE) * STAGE_BYTES;

        LOAD_FRAGS(0, st, 0);
#pragma unroll
        for (int kk2 = 0; kk2 < 4; kk2++) {
            const int cur = kk2 & 1;
            if (kk2 < 3) LOAD_FRAGS(cur ^ 1, st, kk2 + 1);
            MMA_BLOCK(cur);
        }
    }

    __syncthreads();  // all compute done before repurposing smem

    // --- epilogue: stage into smem, dual coalesced writes ---
    float* Cs = (float*)smem;  // [128][CPAD]
#pragma unroll
    for (int mf = 0; mf < 4; mf++)
#pragma unroll
        for (int nf = 0; nf < 8; nf++) {
            const int rr = wm + mf * 16 + (lane >> 2);
            const int cc = wn + nf * 8 + (lane & 3) * 2;
            Cs[rr * CPAD + cc]           = acc[mf][nf][0];
            Cs[rr * CPAD + cc + 1]       = acc[mf][nf][1];
            Cs[(rr + 8) * CPAD + cc]     = acc[mf][nf][2];
            Cs[(rr + 8) * CPAD + cc + 1] = acc[mf][nf][3];
        }
    __syncthreads();

    float* outb = out + (size_t)b * TLEN * TLEN;

    // direct tile: warp w rows [w*32, w*32+32)
#pragma unroll
    for (int k = 0; k < 32; k++) {
        const int r = wid * 32 + k;
        const float* src = Cs + r * CPAD + lane * 4;
        *(float4*)(outb + (size_t)(row0 + r) * TLEN + col0 + lane * 4) =
            make_float4(src[0], src[1], src[2], src[3]);
    }
    // transposed tile
    if (i != j) {
#pragma unroll
        for (int tk = 0; tk < 32; tk++) {
            const int t = wid * 32 + tk;
            const int s = lane * 4;
            *(float4*)(outb + (size_t)(col0 + t) * TLEN + row0 + s) =
                make_float4(Cs[(s + 0) * CPAD + t], Cs[(s + 1) * CPAD + t],
                            Cs[(s + 2) * CPAD + t], Cs[(s + 3) * CPAD + t]);
        }
    }
}

extern "C" void kernel_launch(void* const* d_in, const int* in_sizes, int n_in,
                              void* d_out, int out_size) {
    const float* X = (const float*)d_in[0];
    float* out = (float*)d_out;

    split_kernel<<<BATCH * TLEN, 128>>>(X);

    static int cfg_done = 0;
    if (!cfg_done) {
        cudaFuncSetAttribute(gemm_kernel, cudaFuncAttributeMaxDynamicSharedMemorySize, SMEM_DYN);
        cfg_done = 1;
    }
    dim3 grid(NPAIRS, BATCH);
    gemm_kernel<<<grid, 128, SMEM_DYN>>>(out);
}

// round 12
// speedup vs baseline: 1.1025x; 1.1025x over previous
#include <cuda_runtime.h>
#include <cuda_fp16.h>
#include <math.h>
#include <stdint.h>

#define BATCH 8
#define TLEN  2048
#define DDIM  512
#define BLK   128
#define BLKK  64
#define NTILE (TLEN / BLK)                  // 16
#define NPAIRS (NTILE * (NTILE + 1) / 2)    // 136
#define NITER (DDIM / BLKK)                 // 8
#define TB    16384                         // operand tile: 128 rows x 128B
#define STAGE_BYTES (2 * TB)                // A, B = 32KB
#define NSTAGE 3
#define TPAD 132                            // transpose staging row pitch (floats)
#define SMEM_DYN (NSTAGE * STAGE_BYTES)     // 96KB (> 128*132*4 = 67.6KB)

__device__ __align__(256) __half g_F[(size_t)BATCH * TLEN * DDIM];

static __device__ __forceinline__ uint32_t smem_u32(const void* p) {
    uint32_t a;
    asm("{ .reg .u64 t; cvta.to.shared.u64 t, %1; cvt.u32.u64 %0, t; }" : "=r"(a) : "l"(p));
    return a;
}

#define CP_ASYNC16(saddr, gptr) \
    asm volatile("cp.async.cg.shared.global [%0], [%1], 16;" :: "r"(saddr), "l"(gptr))
#define CP_COMMIT() asm volatile("cp.async.commit_group;" ::: "memory")
#define CP_WAIT(n)  asm volatile("cp.async.wait_group %0;" :: "n"(n) : "memory")

#define LDSM4(R, addr) \
    asm volatile("ldmatrix.sync.aligned.m8n8.x4.shared.b16 {%0,%1,%2,%3}, [%4];" \
        : "=r"((R)[0]), "=r"((R)[1]), "=r"((R)[2]), "=r"((R)[3]) : "r"(addr))

#define MMA16816(d, a, b0, b1) \
    asm volatile("mma.sync.aligned.m16n8k16.row.col.f32.f16.f16.f32 " \
        "{%0,%1,%2,%3},{%4,%5,%6,%7},{%8,%9},{%0,%1,%2,%3};" \
        : "+f"((d)[0]), "+f"((d)[1]), "+f"((d)[2]), "+f"((d)[3]) \
        : "r"((a)[0]), "r"((a)[1]), "r"((a)[2]), "r"((a)[3]), "r"(b0), "r"(b1))

// ---------------------------------------------------------------------------
// Kernel 1: per-row normalize -> fp16. Warp per row, 8 rows per block.
// ---------------------------------------------------------------------------
__global__ void __launch_bounds__(256) split_kernel(const float* __restrict__ X) {
    const int row  = blockIdx.x * 8 + (threadIdx.x >> 5);
    const int lane = threadIdx.x & 31;
    const float4* xr = (const float4*)(X + (size_t)row * DDIM);

    float4 v[4];
#pragma unroll
    for (int q = 0; q < 4; q++) v[q] = xr[lane + q * 32];

    float s = 0.f;
#pragma unroll
    for (int q = 0; q < 4; q++)
        s += v[q].x * v[q].x + v[q].y * v[q].y + v[q].z * v[q].z + v[q].w * v[q].w;
#pragma unroll
    for (int o = 16; o; o >>= 1) s += __shfl_xor_sync(0xffffffffu, s, o);

    const float rn = 1.0f / fmaxf(sqrtf(s), 1e-12f);

    __half2* Fp = (__half2*)(g_F + (size_t)row * DDIM);
#pragma unroll
    for (int q = 0; q < 4; q++) {
        const int idx = (lane + q * 32) * 2;  // half2 index
        Fp[idx]     = __floats2half2_rn(v[q].x * rn, v[q].y * rn);
        Fp[idx + 1] = __floats2half2_rn(v[q].z * rn, v[q].w * rn);
    }
}

// ---------------------------------------------------------------------------
// Kernel 2: C = F F^T, fp16 HMMA
// 4 warps of 64x64; BLKK=64; single-sync 3-stage pipeline; reg-direct epilogue
// ---------------------------------------------------------------------------
__global__ void __launch_bounds__(128, 2) gemm_kernel(float* __restrict__ out) {
    extern __shared__ __align__(1024) char smem[];
    const uint32_t sbase = smem_u32(smem);

    const int tid  = threadIdx.x;
    const int wid  = tid >> 5;
    const int lane = tid & 31;
    const int b    = blockIdx.y;
    const int lin  = blockIdx.x;

    int j = (int)((sqrtf(8.0f * (float)lin + 1.0f) - 1.0f) * 0.5f);
    while ((j + 1) * (j + 2) / 2 <= lin) j++;
    while (j * (j + 1) / 2 > lin) j--;
    const int i = lin - j * (j + 1) / 2;
    const int row0 = i * BLK;
    const int col0 = j * BLK;

    const __half* Fb = g_F + (size_t)b * TLEN * DDIM;

    const int c  = tid & 7;   // 16B chunk within 128B row
    const int r0 = tid >> 3;  // 0..15

#define ISSUE(itr) do {                                                        \
        const int kk_ = (itr) * BLKK;                                          \
        const uint32_t st_ = sbase + ((itr) % NSTAGE) * STAGE_BYTES;           \
        _Pragma("unroll")                                                      \
        for (int q = 0; q < 8; q++) {                                          \
            const int r = r0 + q * 16;                                         \
            const uint32_t so = (uint32_t)(r * 128 + ((c ^ (r & 7)) << 4));    \
            CP_ASYNC16(st_ + so,      Fb + (size_t)(row0 + r) * DDIM + kk_ + c * 8); \
            CP_ASYNC16(st_ + TB + so, Fb + (size_t)(col0 + r) * DDIM + kk_ + c * 8); \
        }                                                                      \
        CP_COMMIT();                                                           \
    } while (0)

    ISSUE(0); ISSUE(1);

    // warp grid: 2(m) x 2(n); warp tile 64(m) x 64(n)
    const int wm = (wid >> 1) * 64;
    const int wn = (wid & 1) * 64;
    const int lrow  = lane & 15;
    const int khalf = lane >> 4;

    float acc[4][8][4];
#pragma unroll
    for (int mf = 0; mf < 4; mf++)
#pragma unroll
        for (int nf = 0; nf < 8; nf++)
#pragma unroll
            for (int u = 0; u < 4; u++) acc[mf][nf][u] = 0.f;

    for (int it = 0; it < NITER; it++) {
        CP_WAIT(1);
        __syncthreads();
        if (it + 2 < NITER) ISSUE(it + 2);

        const uint32_t st = sbase + (it % NSTAGE) * STAGE_BYTES;
#pragma unroll
        for (int kk2 = 0; kk2 < 4; kk2++) {
            const int chunk0 = kk2 * 2 + khalf;
            uint32_t ah[4][4], bx[4][4];
#pragma unroll
            for (int mf = 0; mf < 4; mf++) {
                const int row = wm + mf * 16 + lrow;
                const uint32_t off = row * 128 + ((chunk0 ^ (row & 7)) << 4);
                LDSM4(ah[mf], st + off);
            }
#pragma unroll
            for (int g = 0; g < 4; g++) {
                const int row = wn + g * 16 + lrow;
                const uint32_t off = row * 128 + ((chunk0 ^ (row & 7)) << 4);
                LDSM4(bx[g], st + TB + off);
            }
#pragma unroll
            for (int mf = 0; mf < 4; mf++)
#pragma unroll
                for (int nf = 0; nf < 8; nf++) {
                    const int g = nf >> 1, o = nf & 1;
                    MMA16816(acc[mf][nf], ah[mf], bx[g][o], bx[g][o + 2]);
                }
        }
    }

    float* outb = out + (size_t)b * TLEN * TLEN;

    // --- direct tile straight from registers (32B sectors per 4-lane group) ---
#pragma unroll
    for (int mf = 0; mf < 4; mf++) {
        const int rr = wm + mf * 16 + (lane >> 2);
#pragma unroll
        for (int nf = 0; nf < 8; nf++) {
            const int cc = wn + nf * 8 + (lane & 3) * 2;
            *(float2*)(outb + (size_t)(row0 + rr) * TLEN + col0 + cc) =
                make_float2(acc[mf][nf][0], acc[mf][nf][1]);
            *(float2*)(outb + (size_t)(row0 + rr + 8) * TLEN + col0 + cc) =
                make_float2(acc[mf][nf][2], acc[mf][nf][3]);
        }
    }

    // --- transposed tile via transposed staging (conflict-free both ways) ---
    if (i != j) {
        float* Ct = (float*)smem;  // [128][TPAD], Ct[col][row]
        __syncthreads();  // mainloop smem reads complete before overwrite
#pragma unroll
        for (int mf = 0; mf < 4; mf++) {
            const int rr = wm + mf * 16 + (lane >> 2);
#pragma unroll
            for (int nf = 0; nf < 8; nf++) {
                const int cc = wn + nf * 8 + (lane & 3) * 2;
                Ct[cc * TPAD + rr]           = acc[mf][nf][0];
                Ct[(cc + 1) * TPAD + rr]     = acc[mf][nf][1];
                Ct[cc * TPAD + rr + 8]       = acc[mf][nf][2];
                Ct[(cc + 1) * TPAD + rr + 8] = acc[mf][nf][3];
            }
        }
        __syncthreads();
#pragma unroll
        for (int tk = 0; tk < 32; tk++) {
            const int t = wid * 32 + tk;
            const float4 v = *(const float4*)(Ct + t * TPAD + lane * 4);
            *(float4*)(outb + (size_t)(col0 + t) * TLEN + row0 + lane * 4) = v;
        }
    }
}

extern "C" void kernel_launch(void* const* d_in, const int* in_sizes, int n_in,
                              void* d_out, int out_size) {
    const float* X = (const float*)d_in[0];
    float* out = (float*)d_out;

    split_kernel<<<BATCH * TLEN / 8, 256>>>(X);

    static int cfg_done = 0;
    if (!cfg_done) {
        cudaFuncSetAttribute(gemm_kernel, cudaFuncAttributeMaxDynamicSharedMemorySize, SMEM_DYN);
        cfg_done = 1;
    }
    dim3 grid(NPAIRS, BATCH);
    gemm_kernel<<<grid, 128, SMEM_DYN>>>(out);
}